// round 14
// baseline (speedup 1.0000x reference)
#include <cuda_runtime.h>
#include <math.h>

// GCN 2-layer: out = Â(relu(Â(xW1)+b1))W2 + b2  with Â = D^-1/2 (A+I) D^-1/2
//   0) detect edge_index dtype (int32 vs int64) on-device
//   1) degree + dinv + CSR (by dst) built per launch (int atomics only)
//   2) GEMM1: h1 = x@W1  (packed f32x2 FMA — 2 FLOP/issue, R9: scalar was bound)
//   3) agg1:  g  = relu(Â h1 + b1)   (warp-per-node pull, lane=feature)
//   4) agg2:  a2 = Â g               (uses (Âg)W2 == Â(gW2))
//   5) GEMM2: out = a2@W2 + b2

#define NMAX 100000
#define EMAX 1600000

typedef unsigned long long ull;

__device__ int   g_is64;
__device__ int   g_deg[NMAX];
__device__ float g_dinv[NMAX];
__device__ int   g_rowptr[NMAX + 1];
__device__ int   g_cursor[NMAX];
__device__ int   g_csr[EMAX];
__device__ __align__(16) float g_h1[(size_t)NMAX * 32];
__device__ __align__(16) float g_g [(size_t)NMAX * 32];
__device__ __align__(16) float g_a2[(size_t)NMAX * 32];

// ---------------------------------------------------------------- dtype detect

__global__ void k_detect(const int* __restrict__ w, int E) {
    __shared__ int nonzero;
    if (threadIdx.x == 0) nonzero = 0;
    __syncthreads();
    long long stride = (long long)E / 256 + 1;
    long long p = (long long)threadIdx.x * stride;
    if (p < E) {
        if (w[2 * p + 1] != 0) atomicOr(&nonzero, 1);
    }
    __syncthreads();
    if (threadIdx.x == 0) g_is64 = nonzero ? 0 : 1;
}

__device__ __forceinline__ int load_idx(const void* ei, size_t pos) {
    if (g_is64) return (int)((const long long*)ei)[pos];
    return ((const int*)ei)[pos];
}

// ---------------------------------------------------------------- CSR build

__global__ void k_init_deg(int M) {
    int i = blockIdx.x * blockDim.x + threadIdx.x;
    if (i < M) g_deg[i] = 1;  // self-loop
}

__global__ void k_count(const void* __restrict__ ei, int E) {
    int e = blockIdx.x * blockDim.x + threadIdx.x;
    if (e < E) {
        int d = load_idx(ei, (size_t)E + e);
        atomicAdd(&g_deg[d], 1);
    }
}

// --------- 3-phase exclusive scan of (deg-1) over M elements ---------

#define SCAN_T 256
#define SCAN_I 4
#define SCAN_C (SCAN_T * SCAN_I)
#define SCAN_NB ((NMAX + SCAN_C - 1) / SCAN_C)

__device__ int g_bsum[SCAN_NB];
__device__ int g_boff[SCAN_NB];

__global__ __launch_bounds__(SCAN_T) void k_scan1(int M) {
    __shared__ int red[SCAN_T / 32];
    int b = blockIdx.x, t = threadIdx.x;
    int base = b * SCAN_C + t * SCAN_I;
    int s = 0;
#pragma unroll
    for (int i = 0; i < SCAN_I; i++) {
        int idx = base + i;
        if (idx < M) s += g_deg[idx] - 1;
    }
#pragma unroll
    for (int o = 16; o; o >>= 1) s += __shfl_down_sync(0xffffffffu, s, o);
    if ((t & 31) == 0) red[t >> 5] = s;
    __syncthreads();
    if (t == 0) {
        int tot = 0;
#pragma unroll
        for (int i = 0; i < SCAN_T / 32; i++) tot += red[i];
        g_bsum[b] = tot;
    }
}

__global__ __launch_bounds__(128) void k_scan2(int nb) {
    __shared__ int ps[128];
    int t = threadIdx.x;
    int v = (t < nb) ? g_bsum[t] : 0;
    ps[t] = v;
    __syncthreads();
    for (int o = 1; o < 128; o <<= 1) {
        int u = (t >= o) ? ps[t - o] : 0;
        __syncthreads();
        ps[t] += u;
        __syncthreads();
    }
    if (t < nb) g_boff[t] = ps[t] - v;  // exclusive
}

__global__ __launch_bounds__(SCAN_T) void k_scan3(int M) {
    __shared__ int woff[SCAN_T / 32];
    int b = blockIdx.x, t = threadIdx.x;
    int lane = t & 31, w = t >> 5;
    int base = b * SCAN_C + t * SCAN_I;
    int vals[SCAN_I];
    int s = 0;
#pragma unroll
    for (int i = 0; i < SCAN_I; i++) {
        int idx = base + i;
        int d = (idx < M) ? g_deg[idx] : 1;
        vals[i] = d - 1;
        s += d - 1;
    }
    int sc = s;
#pragma unroll
    for (int o = 1; o < 32; o <<= 1) {
        int u = __shfl_up_sync(0xffffffffu, sc, o);
        if (lane >= o) sc += u;
    }
    if (lane == 31) woff[w] = sc;
    __syncthreads();
    if (t == 0) {
        int run = 0;
#pragma unroll
        for (int i = 0; i < SCAN_T / 32; i++) {
            int v = woff[i];
            woff[i] = run;
            run += v;
        }
    }
    __syncthreads();
    int off = g_boff[b] + woff[w] + (sc - s);
#pragma unroll
    for (int i = 0; i < SCAN_I; i++) {
        int idx = base + i;
        if (idx < M) {
            g_rowptr[idx] = off;
            g_cursor[idx] = off;
            g_dinv[idx] = rsqrtf((float)(vals[i] + 1));
            off += vals[i];
            if (idx == M - 1) g_rowptr[M] = off;
        }
    }
}

__global__ void k_fill(const void* __restrict__ ei, int E) {
    int e = blockIdx.x * blockDim.x + threadIdx.x;
    if (e < E) {
        int s = load_idx(ei, (size_t)e);
        int d = load_idx(ei, (size_t)E + e);
        int p = atomicAdd(&g_cursor[d], 1);
        g_csr[p] = s;
    }
}

// ---------------------------------------------------------------- GEMM1
// h1[M,32] = x[M,512] @ W1[512,32] — packed fma.rn.f32x2 (2 FLOP per issue).
// Block: 256 threads, BM=128 rows, K chunk 64. Thread tile: 2 rows x 8 cols
// (= 2x4 f32x2 accumulators). Static shared: ws 8KB + xs 34KB = 43KB.

#define G1_BM  128
#define G1_KC  64
#define G1_LDX 68  // floats per xs row (pad: conflict-free, 16B-aligned)

__device__ __forceinline__ void fma2(ull& d, ull a, ull b) {
    asm("fma.rn.f32x2 %0, %1, %2, %0;" : "+l"(d) : "l"(a), "l"(b));
}
__device__ __forceinline__ ull dup2(float x) {
    ull r;
    asm("mov.b64 %0, {%1, %1};" : "=l"(r) : "f"(x));
    return r;
}

__global__ __launch_bounds__(256) void k_gemm1(const float* __restrict__ x,
                                               const float* __restrict__ W, int M) {
    __shared__ float ws[G1_KC * 32];
    __shared__ float xs[G1_BM * G1_LDX];
    int tid = threadIdx.x;
    int row0 = blockIdx.x * G1_BM;
    int cg = tid & 3, rg = tid >> 2;
    ull acc[2][4];
#pragma unroll
    for (int i = 0; i < 2; i++)
#pragma unroll
        for (int c = 0; c < 4; c++) acc[i][c] = 0ULL;

    for (int k0 = 0; k0 < 512; k0 += G1_KC) {
        __syncthreads();
        {   // W chunk: 64 x 32 = 512 float4 (2 per thread)
            const float4* W4 = (const float4*)(W + (size_t)k0 * 32);
            float4* S4 = (float4*)ws;
            S4[tid]       = W4[tid];
            S4[tid + 256] = W4[tid + 256];
        }
#pragma unroll
        for (int p = 0; p < 8; p++) {  // x chunk: 128 x 64 = 2048 float4
            int idx = p * 256 + tid;
            int r = idx >> 4;          // 16 float4 per row
            int f = idx & 15;
            int gr = min(row0 + r, M - 1);
            float4 v = *(const float4*)(x + (size_t)gr * 512 + k0 + f * 4);
            *(float4*)&xs[r * G1_LDX + f * 4] = v;
        }
        __syncthreads();
#pragma unroll
        for (int kk = 0; kk < G1_KC; kk += 4) {
            float4 xa4 = *(const float4*)&xs[(rg * 2 + 0) * G1_LDX + kk];
            float4 xb4 = *(const float4*)&xs[(rg * 2 + 1) * G1_LDX + kk];
            float xa[4] = {xa4.x, xa4.y, xa4.z, xa4.w};
            float xb[4] = {xb4.x, xb4.y, xb4.z, xb4.w};
#pragma unroll
            for (int j = 0; j < 4; j++) {
                const ulonglong2* wr =
                    (const ulonglong2*)&ws[(kk + j) * 32 + cg * 8];
                ulonglong2 wA = wr[0];
                ulonglong2 wB = wr[1];
                ull va = dup2(xa[j]);
                ull vb = dup2(xb[j]);
                fma2(acc[0][0], va, wA.x); fma2(acc[0][1], va, wA.y);
                fma2(acc[0][2], va, wB.x); fma2(acc[0][3], va, wB.y);
                fma2(acc[1][0], vb, wA.x); fma2(acc[1][1], vb, wA.y);
                fma2(acc[1][2], vb, wB.x); fma2(acc[1][3], vb, wB.y);
            }
        }
    }
#pragma unroll
    for (int i = 0; i < 2; i++) {
        int row = row0 + rg * 2 + i;
        if (row < M) {
            ull* o = (ull*)&g_h1[(size_t)row * 32 + cg * 8];
            o[0] = acc[i][0]; o[1] = acc[i][1];
            o[2] = acc[i][2]; o[3] = acc[i][3];
        }
    }
}

// ---------------------------------------------------------------- aggregation
// Warp per node, lane = feature (HID=32). Pull from CSR; self-loop folded.
// mode 0: h1 -> g with bias b1 + relu; mode 1: g -> a2, no bias, no relu.

__global__ __launch_bounds__(256) void k_agg(const float* __restrict__ bias,
                                             int mode, int M) {
    const float* __restrict__ hin = (mode == 0) ? g_h1 : g_g;
    float* __restrict__ hout = (mode == 0) ? g_g : g_a2;
    int gw = (blockIdx.x * blockDim.x + threadIdx.x) >> 5;
    int lane = threadIdx.x & 31;
    if (gw >= M) return;
    float di = g_dinv[gw];
    float sum = hin[(size_t)gw * 32 + lane] * di;  // self contribution
    int s = g_rowptr[gw], e = g_rowptr[gw + 1];
    float a0 = 0.f, a1 = 0.f, a2 = 0.f, a3 = 0.f;
    for (int base = s; base < e; base += 32) {
        int idx = base + lane;
        int u;
        float dv;
        if (idx < e) { u = g_csr[idx]; dv = g_dinv[u]; }
        else         { u = gw;         dv = 0.f;       }
#pragma unroll
        for (int j = 0; j < 32; j++) {
            int uj   = __shfl_sync(0xffffffffu, u, j);
            float nj = __shfl_sync(0xffffffffu, dv, j);
            float v = hin[(size_t)uj * 32 + lane];
            if ((j & 3) == 0)      a0 = fmaf(v, nj, a0);
            else if ((j & 3) == 1) a1 = fmaf(v, nj, a1);
            else if ((j & 3) == 2) a2 = fmaf(v, nj, a2);
            else                   a3 = fmaf(v, nj, a3);
        }
    }
    sum += (a0 + a1) + (a2 + a3);
    float r = sum * di + (bias ? bias[lane] : 0.f);
    if (mode == 0) r = fmaxf(r, 0.f);
    hout[(size_t)gw * 32 + lane] = r;
}

// ---------------------------------------------------------------- GEMM2
// out[M,40] = a2[M,32] @ W2[32,40] + b2. Warp per row, shfl broadcast.

__global__ __launch_bounds__(256) void k_gemm2(const float* __restrict__ W2,
                                               const float* __restrict__ b2,
                                               float* __restrict__ out, int M) {
    __shared__ float ws[32 * 40];
    __shared__ float bs[40];
    int tid = threadIdx.x;
    for (int i = tid; i < 1280; i += 256) ws[i] = W2[i];
    if (tid < 40) bs[tid] = b2[tid];
    __syncthreads();
    int gw = (blockIdx.x * 256 + tid) >> 5;
    int lane = tid & 31;
    if (gw >= M) return;
    float xv = g_a2[(size_t)gw * 32 + lane];
    float acc0 = bs[lane];
    float acc1 = (lane < 8) ? bs[32 + lane] : 0.f;
#pragma unroll
    for (int k = 0; k < 32; k++) {
        float xk = __shfl_sync(0xffffffffu, xv, k);
        acc0 = fmaf(xk, ws[k * 40 + lane], acc0);
        if (lane < 8) acc1 = fmaf(xk, ws[k * 40 + 32 + lane], acc1);
    }
    out[(size_t)gw * 40 + lane] = acc0;
    if (lane < 8) out[(size_t)gw * 40 + 32 + lane] = acc1;
}

// ---------------------------------------------------------------- launch

extern "C" void kernel_launch(void* const* d_in, const int* in_sizes, int n_in,
                              void* d_out, int out_size) {
    const float* x  = (const float*)d_in[0];
    const void*  ei = d_in[1];
    const float* W1 = (const float*)d_in[2];
    const float* b1 = (const float*)d_in[3];
    const float* W2 = (const float*)d_in[4];
    const float* b2 = (const float*)d_in[5];
    float* out = (float*)d_out;

    int M = in_sizes[0] / 512;   // 100000
    int E = in_sizes[1] / 2;     // 1600000

    int nb = (M + SCAN_C - 1) / SCAN_C;

    k_detect<<<1, 256>>>((const int*)ei, E);
    k_init_deg<<<(M + 255) / 256, 256>>>(M);
    k_count<<<(E + 255) / 256, 256>>>(ei, E);
    k_scan1<<<nb, SCAN_T>>>(M);
    k_scan2<<<1, 128>>>(nb);
    k_scan3<<<nb, SCAN_T>>>(M);
    k_fill<<<(E + 255) / 256, 256>>>(ei, E);

    k_gemm1<<<(M + G1_BM - 1) / G1_BM, 256>>>(x, W1, M);

    int ga = (M * 32 + 255) / 256;  // warp per node
    k_agg<<<ga, 256>>>(b1, 0, M);
    k_agg<<<ga, 256>>>(nullptr, 1, M);

    k_gemm2<<<ga, 256>>>(W2, b2, out, M);
}

// round 15
// speedup vs baseline: 1.0724x; 1.0724x over previous
#include <cuda_runtime.h>
#include <math.h>

// GCN 2-layer: out = Â(relu(Â(xW1)+b1))W2 + b2,  Â = D^-1/2 (A+I) D^-1/2
// Key factorization: norm(s,d) = dinv[s]*dinv[d], so rows are pre-scaled by
// dinv once (GEMM1 epilogue / agg1 epilogue) and aggregation is a plain sum.
//   1) CSR build (dtype-detect, count, 3-phase scan, fill)
//   2) GEMM1: h1s = (x@W1) * dinv[row]        (f32x2 FMA, DRAM-bound)
//   3) agg1:  gs  = relu(dinv*Σ h1s[u] + b1) * dinv   (warp/node, lane=feat)
//   4) agg2+GEMM2 fused: out = (dinv*Σ gs[u]) @ W2 + b2

#define NMAX 100000
#define EMAX 1600000

typedef unsigned long long ull;

__device__ int   g_is64;
__device__ int   g_deg[NMAX];
__device__ float g_dinv[NMAX];
__device__ int   g_rowptr[NMAX + 1];
__device__ int   g_cursor[NMAX];
__device__ int   g_csr[EMAX];
__device__ __align__(16) float g_h1[(size_t)NMAX * 32];  // pre-scaled by dinv
__device__ __align__(16) float g_g [(size_t)NMAX * 32];  // pre-scaled by dinv

// ---------------------------------------------------------------- dtype detect

__global__ void k_detect(const int* __restrict__ w, int E) {
    __shared__ int nonzero;
    if (threadIdx.x == 0) nonzero = 0;
    __syncthreads();
    long long stride = (long long)E / 256 + 1;
    long long p = (long long)threadIdx.x * stride;
    if (p < E) {
        if (w[2 * p + 1] != 0) atomicOr(&nonzero, 1);
    }
    __syncthreads();
    if (threadIdx.x == 0) g_is64 = nonzero ? 0 : 1;
}

__device__ __forceinline__ int load_idx(const void* ei, size_t pos) {
    if (g_is64) return (int)((const long long*)ei)[pos];
    return ((const int*)ei)[pos];
}

// ---------------------------------------------------------------- CSR build

__global__ void k_init_deg(int M) {
    int i = blockIdx.x * blockDim.x + threadIdx.x;
    if (i < M) g_deg[i] = 1;  // self-loop
}

__global__ void k_count(const void* __restrict__ ei, int E) {
    int e = blockIdx.x * blockDim.x + threadIdx.x;
    if (e < E) {
        int d = load_idx(ei, (size_t)E + e);
        atomicAdd(&g_deg[d], 1);
    }
}

#define SCAN_T 256
#define SCAN_I 4
#define SCAN_C (SCAN_T * SCAN_I)
#define SCAN_NB ((NMAX + SCAN_C - 1) / SCAN_C)

__device__ int g_bsum[SCAN_NB];
__device__ int g_boff[SCAN_NB];

__global__ __launch_bounds__(SCAN_T) void k_scan1(int M) {
    __shared__ int red[SCAN_T / 32];
    int b = blockIdx.x, t = threadIdx.x;
    int base = b * SCAN_C + t * SCAN_I;
    int s = 0;
#pragma unroll
    for (int i = 0; i < SCAN_I; i++) {
        int idx = base + i;
        if (idx < M) s += g_deg[idx] - 1;
    }
#pragma unroll
    for (int o = 16; o; o >>= 1) s += __shfl_down_sync(0xffffffffu, s, o);
    if ((t & 31) == 0) red[t >> 5] = s;
    __syncthreads();
    if (t == 0) {
        int tot = 0;
#pragma unroll
        for (int i = 0; i < SCAN_T / 32; i++) tot += red[i];
        g_bsum[b] = tot;
    }
}

__global__ __launch_bounds__(128) void k_scan2(int nb) {
    __shared__ int ps[128];
    int t = threadIdx.x;
    int v = (t < nb) ? g_bsum[t] : 0;
    ps[t] = v;
    __syncthreads();
    for (int o = 1; o < 128; o <<= 1) {
        int u = (t >= o) ? ps[t - o] : 0;
        __syncthreads();
        ps[t] += u;
        __syncthreads();
    }
    if (t < nb) g_boff[t] = ps[t] - v;  // exclusive
}

__global__ __launch_bounds__(SCAN_T) void k_scan3(int M) {
    __shared__ int woff[SCAN_T / 32];
    int b = blockIdx.x, t = threadIdx.x;
    int lane = t & 31, w = t >> 5;
    int base = b * SCAN_C + t * SCAN_I;
    int vals[SCAN_I];
    int s = 0;
#pragma unroll
    for (int i = 0; i < SCAN_I; i++) {
        int idx = base + i;
        int d = (idx < M) ? g_deg[idx] : 1;
        vals[i] = d - 1;
        s += d - 1;
    }
    int sc = s;
#pragma unroll
    for (int o = 1; o < 32; o <<= 1) {
        int u = __shfl_up_sync(0xffffffffu, sc, o);
        if (lane >= o) sc += u;
    }
    if (lane == 31) woff[w] = sc;
    __syncthreads();
    if (t == 0) {
        int run = 0;
#pragma unroll
        for (int i = 0; i < SCAN_T / 32; i++) {
            int v = woff[i];
            woff[i] = run;
            run += v;
        }
    }
    __syncthreads();
    int off = g_boff[b] + woff[w] + (sc - s);
#pragma unroll
    for (int i = 0; i < SCAN_I; i++) {
        int idx = base + i;
        if (idx < M) {
            g_rowptr[idx] = off;
            g_cursor[idx] = off;
            g_dinv[idx] = rsqrtf((float)(vals[i] + 1));
            off += vals[i];
            if (idx == M - 1) g_rowptr[M] = off;
        }
    }
}

__global__ void k_fill(const void* __restrict__ ei, int E) {
    int e = blockIdx.x * blockDim.x + threadIdx.x;
    if (e < E) {
        int s = load_idx(ei, (size_t)e);
        int d = load_idx(ei, (size_t)E + e);
        int p = atomicAdd(&g_cursor[d], 1);
        g_csr[p] = s;
    }
}

// ---------------------------------------------------------------- GEMM1
// h1s[M,32] = (x[M,512] @ W1[512,32]) * dinv[row].  f32x2 FMA, DRAM-bound.

#define G1_BM  128
#define G1_KC  64
#define G1_LDX 68

__device__ __forceinline__ void fma2(ull& d, ull a, ull b) {
    asm("fma.rn.f32x2 %0, %1, %2, %0;" : "+l"(d) : "l"(a), "l"(b));
}
__device__ __forceinline__ ull dup2(float x) {
    ull r;
    asm("mov.b64 %0, {%1, %1};" : "=l"(r) : "f"(x));
    return r;
}

__global__ __launch_bounds__(256) void k_gemm1(const float* __restrict__ x,
                                               const float* __restrict__ W, int M) {
    __shared__ float ws[G1_KC * 32];
    __shared__ float xs[G1_BM * G1_LDX];
    int tid = threadIdx.x;
    int row0 = blockIdx.x * G1_BM;
    int cg = tid & 3, rg = tid >> 2;
    ull acc[2][4];
#pragma unroll
    for (int i = 0; i < 2; i++)
#pragma unroll
        for (int c = 0; c < 4; c++) acc[i][c] = 0ULL;

    for (int k0 = 0; k0 < 512; k0 += G1_KC) {
        __syncthreads();
        {
            const float4* W4 = (const float4*)(W + (size_t)k0 * 32);
            float4* S4 = (float4*)ws;
            S4[tid]       = W4[tid];
            S4[tid + 256] = W4[tid + 256];
        }
#pragma unroll
        for (int p = 0; p < 8; p++) {
            int idx = p * 256 + tid;
            int r = idx >> 4;
            int f = idx & 15;
            int gr = min(row0 + r, M - 1);
            float4 v = *(const float4*)(x + (size_t)gr * 512 + k0 + f * 4);
            *(float4*)&xs[r * G1_LDX + f * 4] = v;
        }
        __syncthreads();
#pragma unroll
        for (int kk = 0; kk < G1_KC; kk += 4) {
            float4 xa4 = *(const float4*)&xs[(rg * 2 + 0) * G1_LDX + kk];
            float4 xb4 = *(const float4*)&xs[(rg * 2 + 1) * G1_LDX + kk];
            float xa[4] = {xa4.x, xa4.y, xa4.z, xa4.w};
            float xb[4] = {xb4.x, xb4.y, xb4.z, xb4.w};
#pragma unroll
            for (int j = 0; j < 4; j++) {
                const ulonglong2* wr =
                    (const ulonglong2*)&ws[(kk + j) * 32 + cg * 8];
                ulonglong2 wA = wr[0];
                ulonglong2 wB = wr[1];
                ull va = dup2(xa[j]);
                ull vb = dup2(xb[j]);
                fma2(acc[0][0], va, wA.x); fma2(acc[0][1], va, wA.y);
                fma2(acc[0][2], va, wB.x); fma2(acc[0][3], va, wB.y);
                fma2(acc[1][0], vb, wA.x); fma2(acc[1][1], vb, wA.y);
                fma2(acc[1][2], vb, wB.x); fma2(acc[1][3], vb, wB.y);
            }
        }
    }
#pragma unroll
    for (int i = 0; i < 2; i++) {
        int row = row0 + rg * 2 + i;
        if (row < M) {
            float di = g_dinv[row];
            float o[8];
#pragma unroll
            for (int c = 0; c < 4; c++) {
                o[2 * c]     = __uint_as_float((unsigned)(acc[i][c])) * di;
                o[2 * c + 1] = __uint_as_float((unsigned)(acc[i][c] >> 32)) * di;
            }
            float4* dst = (float4*)&g_h1[(size_t)row * 32 + cg * 8];
            dst[0] = make_float4(o[0], o[1], o[2], o[3]);
            dst[1] = make_float4(o[4], o[5], o[6], o[7]);
        }
    }
}

// ---------------------------------------------------------------- agg1
// gs = relu(dinv * Σ_{u∈N∪self} h1s[u] + b1) * dinv.
// Warp per node, lane = feature. Dynamic batch count: no padded gathers.

__global__ __launch_bounds__(256) void k_agg1(const float* __restrict__ b1, int M) {
    int gw = (blockIdx.x * blockDim.x + threadIdx.x) >> 5;
    int lane = threadIdx.x & 31;
    if (gw >= M) return;
    float di = g_dinv[gw];
    float a0 = g_h1[(size_t)gw * 32 + lane];  // self (pre-scaled)
    float a1 = 0.f, a2 = 0.f, a3 = 0.f;
    int s = g_rowptr[gw], e = g_rowptr[gw + 1];
    for (int base = s; base < e; base += 32) {
        int idx = base + lane;
        int u = (idx < e) ? g_csr[idx] : 0;
        int cnt = min(32, e - base);
        int j = 0;
        for (; j + 4 <= cnt; j += 4) {
            int u0 = __shfl_sync(0xffffffffu, u, j);
            int u1 = __shfl_sync(0xffffffffu, u, j + 1);
            int u2 = __shfl_sync(0xffffffffu, u, j + 2);
            int u3 = __shfl_sync(0xffffffffu, u, j + 3);
            a0 += g_h1[(size_t)u0 * 32 + lane];
            a1 += g_h1[(size_t)u1 * 32 + lane];
            a2 += g_h1[(size_t)u2 * 32 + lane];
            a3 += g_h1[(size_t)u3 * 32 + lane];
        }
        for (; j < cnt; j++) {
            int uj = __shfl_sync(0xffffffffu, u, j);
            a0 += g_h1[(size_t)uj * 32 + lane];
        }
    }
    float r = (a0 + a1) + (a2 + a3);
    r = fmaxf(r * di + b1[lane], 0.f) * di;   // pre-scale for layer 2
    g_g[(size_t)gw * 32 + lane] = r;
}

// ---------------------------------------------------------------- agg2 + GEMM2
// a2 = dinv * Σ gs[u]; out = a2 @ W2 + b2 — fused, a2 never leaves registers.

__global__ __launch_bounds__(256) void k_agg2(const float* __restrict__ W2,
                                              const float* __restrict__ b2,
                                              float* __restrict__ out, int M) {
    __shared__ float ws[32 * 40];
    __shared__ float bs[40];
    int tid = threadIdx.x;
    for (int i = tid; i < 1280; i += 256) ws[i] = W2[i];
    if (tid < 40) bs[tid] = b2[tid];
    __syncthreads();
    int gw = (blockIdx.x * 256 + tid) >> 5;
    int lane = tid & 31;
    if (gw >= M) return;
    float di = g_dinv[gw];
    float a0 = g_g[(size_t)gw * 32 + lane];  // self (pre-scaled)
    float a1 = 0.f, a2 = 0.f, a3 = 0.f;
    int s = g_rowptr[gw], e = g_rowptr[gw + 1];
    for (int base = s; base < e; base += 32) {
        int idx = base + lane;
        int u = (idx < e) ? g_csr[idx] : 0;
        int cnt = min(32, e - base);
        int j = 0;
        for (; j + 4 <= cnt; j += 4) {
            int u0 = __shfl_sync(0xffffffffu, u, j);
            int u1 = __shfl_sync(0xffffffffu, u, j + 1);
            int u2 = __shfl_sync(0xffffffffu, u, j + 2);
            int u3 = __shfl_sync(0xffffffffu, u, j + 3);
            a0 += g_g[(size_t)u0 * 32 + lane];
            a1 += g_g[(size_t)u1 * 32 + lane];
            a2 += g_g[(size_t)u2 * 32 + lane];
            a3 += g_g[(size_t)u3 * 32 + lane];
        }
        for (; j < cnt; j++) {
            int uj = __shfl_sync(0xffffffffu, u, j);
            a0 += g_g[(size_t)uj * 32 + lane];
        }
    }
    float av = ((a0 + a1) + (a2 + a3)) * di;  // a2 row value for feature=lane
    // out row = av @ W2 + b2  (shfl-broadcast tiny GEMM)
    float acc0 = bs[lane];
    float acc1 = (lane < 8) ? bs[32 + lane] : 0.f;
#pragma unroll
    for (int k = 0; k < 32; k++) {
        float xk = __shfl_sync(0xffffffffu, av, k);
        acc0 = fmaf(xk, ws[k * 40 + lane], acc0);
        if (lane < 8) acc1 = fmaf(xk, ws[k * 40 + 32 + lane], acc1);
    }
    out[(size_t)gw * 40 + lane] = acc0;
    if (lane < 8) out[(size_t)gw * 40 + 32 + lane] = acc1;
}

// ---------------------------------------------------------------- launch

extern "C" void kernel_launch(void* const* d_in, const int* in_sizes, int n_in,
                              void* d_out, int out_size) {
    const float* x  = (const float*)d_in[0];
    const void*  ei = d_in[1];
    const float* W1 = (const float*)d_in[2];
    const float* b1 = (const float*)d_in[3];
    const float* W2 = (const float*)d_in[4];
    const float* b2 = (const float*)d_in[5];
    float* out = (float*)d_out;

    int M = in_sizes[0] / 512;   // 100000
    int E = in_sizes[1] / 2;     // 1600000

    int nb = (M + SCAN_C - 1) / SCAN_C;

    k_detect<<<1, 256>>>((const int*)ei, E);
    k_init_deg<<<(M + 255) / 256, 256>>>(M);
    k_count<<<(E + 255) / 256, 256>>>(ei, E);
    k_scan1<<<nb, SCAN_T>>>(M);
    k_scan2<<<1, 128>>>(nb);
    k_scan3<<<nb, SCAN_T>>>(M);
    k_fill<<<(E + 255) / 256, 256>>>(ei, E);

    k_gemm1<<<(M + G1_BM - 1) / G1_BM, 256>>>(x, W1, M);

    int ga = (M * 32 + 255) / 256;  // warp per node
    k_agg1<<<ga, 256>>>(b1, M);
    k_agg2<<<ga, 256>>>(W2, b2, out, M);
}

// round 16
// speedup vs baseline: 1.1203x; 1.0446x over previous
#include <cuda_runtime.h>
#include <math.h>

// GCN 2-layer: out = Â(relu(Â(xW1)+b1))W2 + b2,  Â = D^-1/2 (A+I) D^-1/2
// Key factorization: norm(s,d) = dinv[s]*dinv[d], so rows are pre-scaled by
// dinv once (GEMM1 epilogue / agg1 epilogue) and aggregation is a plain sum.
//   1) CSR build (dtype-detect, count, 3-phase scan, fill)
//   2) GEMM1: h1s = (x@W1) * dinv[row]        (f32x2 FMA, DRAM-bound)
//   3) agg1:  gs  = relu(dinv*Σ h1s[u] + b1) * dinv   (warp/node, lane=feat)
//   4) agg2+GEMM2 fused: out = (dinv*Σ gs[u]) @ W2 + b2

#define NMAX 100000
#define EMAX 1600000

typedef unsigned long long ull;

__device__ int   g_is64;
__device__ int   g_deg[NMAX];
__device__ float g_dinv[NMAX];
__device__ int   g_rowptr[NMAX + 1];
__device__ int   g_cursor[NMAX];
__device__ int   g_csr[EMAX];
__device__ __align__(16) float g_h1[(size_t)NMAX * 32];  // pre-scaled by dinv
__device__ __align__(16) float g_g [(size_t)NMAX * 32];  // pre-scaled by dinv

// ---------------------------------------------------------------- dtype detect

__global__ void k_detect(const int* __restrict__ w, int E) {
    __shared__ int nonzero;
    if (threadIdx.x == 0) nonzero = 0;
    __syncthreads();
    long long stride = (long long)E / 256 + 1;
    long long p = (long long)threadIdx.x * stride;
    if (p < E) {
        if (w[2 * p + 1] != 0) atomicOr(&nonzero, 1);
    }
    __syncthreads();
    if (threadIdx.x == 0) g_is64 = nonzero ? 0 : 1;
}

__device__ __forceinline__ int load_idx(const void* ei, size_t pos) {
    if (g_is64) return (int)((const long long*)ei)[pos];
    return ((const int*)ei)[pos];
}

// ---------------------------------------------------------------- CSR build

__global__ void k_init_deg(int M) {
    int i = blockIdx.x * blockDim.x + threadIdx.x;
    if (i < M) g_deg[i] = 1;  // self-loop
}

__global__ void k_count(const void* __restrict__ ei, int E) {
    int e = blockIdx.x * blockDim.x + threadIdx.x;
    if (e < E) {
        int d = load_idx(ei, (size_t)E + e);
        atomicAdd(&g_deg[d], 1);
    }
}

#define SCAN_T 256
#define SCAN_I 4
#define SCAN_C (SCAN_T * SCAN_I)
#define SCAN_NB ((NMAX + SCAN_C - 1) / SCAN_C)

__device__ int g_bsum[SCAN_NB];
__device__ int g_boff[SCAN_NB];

__global__ __launch_bounds__(SCAN_T) void k_scan1(int M) {
    __shared__ int red[SCAN_T / 32];
    int b = blockIdx.x, t = threadIdx.x;
    int base = b * SCAN_C + t * SCAN_I;
    int s = 0;
#pragma unroll
    for (int i = 0; i < SCAN_I; i++) {
        int idx = base + i;
        if (idx < M) s += g_deg[idx] - 1;
    }
#pragma unroll
    for (int o = 16; o; o >>= 1) s += __shfl_down_sync(0xffffffffu, s, o);
    if ((t & 31) == 0) red[t >> 5] = s;
    __syncthreads();
    if (t == 0) {
        int tot = 0;
#pragma unroll
        for (int i = 0; i < SCAN_T / 32; i++) tot += red[i];
        g_bsum[b] = tot;
    }
}

__global__ __launch_bounds__(128) void k_scan2(int nb) {
    __shared__ int ps[128];
    int t = threadIdx.x;
    int v = (t < nb) ? g_bsum[t] : 0;
    ps[t] = v;
    __syncthreads();
    for (int o = 1; o < 128; o <<= 1) {
        int u = (t >= o) ? ps[t - o] : 0;
        __syncthreads();
        ps[t] += u;
        __syncthreads();
    }
    if (t < nb) g_boff[t] = ps[t] - v;  // exclusive
}

__global__ __launch_bounds__(SCAN_T) void k_scan3(int M) {
    __shared__ int woff[SCAN_T / 32];
    int b = blockIdx.x, t = threadIdx.x;
    int lane = t & 31, w = t >> 5;
    int base = b * SCAN_C + t * SCAN_I;
    int vals[SCAN_I];
    int s = 0;
#pragma unroll
    for (int i = 0; i < SCAN_I; i++) {
        int idx = base + i;
        int d = (idx < M) ? g_deg[idx] : 1;
        vals[i] = d - 1;
        s += d - 1;
    }
    int sc = s;
#pragma unroll
    for (int o = 1; o < 32; o <<= 1) {
        int u = __shfl_up_sync(0xffffffffu, sc, o);
        if (lane >= o) sc += u;
    }
    if (lane == 31) woff[w] = sc;
    __syncthreads();
    if (t == 0) {
        int run = 0;
#pragma unroll
        for (int i = 0; i < SCAN_T / 32; i++) {
            int v = woff[i];
            woff[i] = run;
            run += v;
        }
    }
    __syncthreads();
    int off = g_boff[b] + woff[w] + (sc - s);
#pragma unroll
    for (int i = 0; i < SCAN_I; i++) {
        int idx = base + i;
        if (idx < M) {
            g_rowptr[idx] = off;
            g_cursor[idx] = off;
            g_dinv[idx] = rsqrtf((float)(vals[i] + 1));
            off += vals[i];
            if (idx == M - 1) g_rowptr[M] = off;
        }
    }
}

__global__ void k_fill(const void* __restrict__ ei, int E) {
    int e = blockIdx.x * blockDim.x + threadIdx.x;
    if (e < E) {
        int s = load_idx(ei, (size_t)e);
        int d = load_idx(ei, (size_t)E + e);
        int p = atomicAdd(&g_cursor[d], 1);
        g_csr[p] = s;
    }
}

// ---------------------------------------------------------------- GEMM1
// h1s[M,32] = (x[M,512] @ W1[512,32]) * dinv[row].  f32x2 FMA, DRAM-bound.

#define G1_BM  128
#define G1_KC  64
#define G1_LDX 68

__device__ __forceinline__ void fma2(ull& d, ull a, ull b) {
    asm("fma.rn.f32x2 %0, %1, %2, %0;" : "+l"(d) : "l"(a), "l"(b));
}
__device__ __forceinline__ ull dup2(float x) {
    ull r;
    asm("mov.b64 %0, {%1, %1};" : "=l"(r) : "f"(x));
    return r;
}

__global__ __launch_bounds__(256) void k_gemm1(const float* __restrict__ x,
                                               const float* __restrict__ W, int M) {
    __shared__ float ws[G1_KC * 32];
    __shared__ float xs[G1_BM * G1_LDX];
    int tid = threadIdx.x;
    int row0 = blockIdx.x * G1_BM;
    int cg = tid & 3, rg = tid >> 2;
    ull acc[2][4];
#pragma unroll
    for (int i = 0; i < 2; i++)
#pragma unroll
        for (int c = 0; c < 4; c++) acc[i][c] = 0ULL;

    for (int k0 = 0; k0 < 512; k0 += G1_KC) {
        __syncthreads();
        {
            const float4* W4 = (const float4*)(W + (size_t)k0 * 32);
            float4* S4 = (float4*)ws;
            S4[tid]       = W4[tid];
            S4[tid + 256] = W4[tid + 256];
        }
#pragma unroll
        for (int p = 0; p < 8; p++) {
            int idx = p * 256 + tid;
            int r = idx >> 4;
            int f = idx & 15;
            int gr = min(row0 + r, M - 1);
            float4 v = *(const float4*)(x + (size_t)gr * 512 + k0 + f * 4);
            *(float4*)&xs[r * G1_LDX + f * 4] = v;
        }
        __syncthreads();
#pragma unroll
        for (int kk = 0; kk < G1_KC; kk += 4) {
            float4 xa4 = *(const float4*)&xs[(rg * 2 + 0) * G1_LDX + kk];
            float4 xb4 = *(const float4*)&xs[(rg * 2 + 1) * G1_LDX + kk];
            float xa[4] = {xa4.x, xa4.y, xa4.z, xa4.w};
            float xb[4] = {xb4.x, xb4.y, xb4.z, xb4.w};
#pragma unroll
            for (int j = 0; j < 4; j++) {
                const ulonglong2* wr =
                    (const ulonglong2*)&ws[(kk + j) * 32 + cg * 8];
                ulonglong2 wA = wr[0];
                ulonglong2 wB = wr[1];
                ull va = dup2(xa[j]);
                ull vb = dup2(xb[j]);
                fma2(acc[0][0], va, wA.x); fma2(acc[0][1], va, wA.y);
                fma2(acc[0][2], va, wB.x); fma2(acc[0][3], va, wB.y);
                fma2(acc[1][0], vb, wA.x); fma2(acc[1][1], vb, wA.y);
                fma2(acc[1][2], vb, wB.x); fma2(acc[1][3], vb, wB.y);
            }
        }
    }
#pragma unroll
    for (int i = 0; i < 2; i++) {
        int row = row0 + rg * 2 + i;
        if (row < M) {
            float di = g_dinv[row];
            float o[8];
#pragma unroll
            for (int c = 0; c < 4; c++) {
                o[2 * c]     = __uint_as_float((unsigned)(acc[i][c])) * di;
                o[2 * c + 1] = __uint_as_float((unsigned)(acc[i][c] >> 32)) * di;
            }
            float4* dst = (float4*)&g_h1[(size_t)row * 32 + cg * 8];
            dst[0] = make_float4(o[0], o[1], o[2], o[3]);
            dst[1] = make_float4(o[4], o[5], o[6], o[7]);
        }
    }
}

// ---------------------------------------------------------------- agg1
// gs = relu(dinv * Σ_{u∈N∪self} h1s[u] + b1) * dinv.
// Warp per node, lane = feature. Dynamic batch count: no padded gathers.

__global__ __launch_bounds__(256) void k_agg1(const float* __restrict__ b1, int M) {
    int gw = (blockIdx.x * blockDim.x + threadIdx.x) >> 5;
    int lane = threadIdx.x & 31;
    if (gw >= M) return;
    float di = g_dinv[gw];
    float a0 = g_h1[(size_t)gw * 32 + lane];  // self (pre-scaled)
    float a1 = 0.f, a2 = 0.f, a3 = 0.f;
    int s = g_rowptr[gw], e = g_rowptr[gw + 1];
    for (int base = s; base < e; base += 32) {
        int idx = base + lane;
        int u = (idx < e) ? g_csr[idx] : 0;
        int cnt = min(32, e - base);
        int j = 0;
        for (; j + 4 <= cnt; j += 4) {
            int u0 = __shfl_sync(0xffffffffu, u, j);
            int u1 = __shfl_sync(0xffffffffu, u, j + 1);
            int u2 = __shfl_sync(0xffffffffu, u, j + 2);
            int u3 = __shfl_sync(0xffffffffu, u, j + 3);
            a0 += g_h1[(size_t)u0 * 32 + lane];
            a1 += g_h1[(size_t)u1 * 32 + lane];
            a2 += g_h1[(size_t)u2 * 32 + lane];
            a3 += g_h1[(size_t)u3 * 32 + lane];
        }
        for (; j < cnt; j++) {
            int uj = __shfl_sync(0xffffffffu, u, j);
            a0 += g_h1[(size_t)uj * 32 + lane];
        }
    }
    float r = (a0 + a1) + (a2 + a3);
    r = fmaxf(r * di + b1[lane], 0.f) * di;   // pre-scale for layer 2
    g_g[(size_t)gw * 32 + lane] = r;
}

// ---------------------------------------------------------------- agg2 + GEMM2
// a2 = dinv * Σ gs[u]; out = a2 @ W2 + b2 — fused, a2 never leaves registers.

__global__ __launch_bounds__(256) void k_agg2(const float* __restrict__ W2,
                                              const float* __restrict__ b2,
                                              float* __restrict__ out, int M) {
    __shared__ float ws[32 * 40];
    __shared__ float bs[40];
    int tid = threadIdx.x;
    for (int i = tid; i < 1280; i += 256) ws[i] = W2[i];
    if (tid < 40) bs[tid] = b2[tid];
    __syncthreads();
    int gw = (blockIdx.x * 256 + tid) >> 5;
    int lane = tid & 31;
    if (gw >= M) return;
    float di = g_dinv[gw];
    float a0 = g_g[(size_t)gw * 32 + lane];  // self (pre-scaled)
    float a1 = 0.f, a2 = 0.f, a3 = 0.f;
    int s = g_rowptr[gw], e = g_rowptr[gw + 1];
    for (int base = s; base < e; base += 32) {
        int idx = base + lane;
        int u = (idx < e) ? g_csr[idx] : 0;
        int cnt = min(32, e - base);
        int j = 0;
        for (; j + 4 <= cnt; j += 4) {
            int u0 = __shfl_sync(0xffffffffu, u, j);
            int u1 = __shfl_sync(0xffffffffu, u, j + 1);
            int u2 = __shfl_sync(0xffffffffu, u, j + 2);
            int u3 = __shfl_sync(0xffffffffu, u, j + 3);
            a0 += g_g[(size_t)u0 * 32 + lane];
            a1 += g_g[(size_t)u1 * 32 + lane];
            a2 += g_g[(size_t)u2 * 32 + lane];
            a3 += g_g[(size_t)u3 * 32 + lane];
        }
        for (; j < cnt; j++) {
            int uj = __shfl_sync(0xffffffffu, u, j);
            a0 += g_g[(size_t)uj * 32 + lane];
        }
    }
    float av = ((a0 + a1) + (a2 + a3)) * di;  // a2 row value for feature=lane
    // out row = av @ W2 + b2  (shfl-broadcast tiny GEMM)
    float acc0 = bs[lane];
    float acc1 = (lane < 8) ? bs[32 + lane] : 0.f;
#pragma unroll
    for (int k = 0; k < 32; k++) {
        float xk = __shfl_sync(0xffffffffu, av, k);
        acc0 = fmaf(xk, ws[k * 40 + lane], acc0);
        if (lane < 8) acc1 = fmaf(xk, ws[k * 40 + 32 + lane], acc1);
    }
    out[(size_t)gw * 40 + lane] = acc0;
    if (lane < 8) out[(size_t)gw * 40 + 32 + lane] = acc1;
}

// ---------------------------------------------------------------- launch

extern "C" void kernel_launch(void* const* d_in, const int* in_sizes, int n_in,
                              void* d_out, int out_size) {
    const float* x  = (const float*)d_in[0];
    const void*  ei = d_in[1];
    const float* W1 = (const float*)d_in[2];
    const float* b1 = (const float*)d_in[3];
    const float* W2 = (const float*)d_in[4];
    const float* b2 = (const float*)d_in[5];
    float* out = (float*)d_out;

    int M = in_sizes[0] / 512;   // 100000
    int E = in_sizes[1] / 2;     // 1600000

    int nb = (M + SCAN_C - 1) / SCAN_C;

    k_detect<<<1, 256>>>((const int*)ei, E);
    k_init_deg<<<(M + 255) / 256, 256>>>(M);
    k_count<<<(E + 255) / 256, 256>>>(ei, E);
    k_scan1<<<nb, SCAN_T>>>(M);
    k_scan2<<<1, 128>>>(nb);
    k_scan3<<<nb, SCAN_T>>>(M);
    k_fill<<<(E + 255) / 256, 256>>>(ei, E);

    k_gemm1<<<(M + G1_BM - 1) / G1_BM, 256>>>(x, W1, M);

    int ga = (M * 32 + 255) / 256;  // warp per node
    k_agg1<<<ga, 256>>>(b1, M);
    k_agg2<<<ga, 256>>>(W2, b2, out, M);
}